// round 11
// baseline (speedup 1.0000x reference)
#include <cuda_runtime.h>
#include <cuda_fp16.h>
#include <math.h>
#include <stdint.h>

#define NN 8192
#define DD 256
#define FF 128
#define BB 4096
#define JSPLIT 16
#define MAXT 32
#define MAXU (MAXT * JSPLIT)   // 512

#define SA_HI 0
#define SA_LO 32768
#define SJB(b) (65536 + (b) * 65536)
#define SMSK 196608                    // adjacency masks: 128 rows x 20 words (80 B stride)
#define SM_TOTAL (196608 + 10240)

// ---------------- device scratch ----------------
__device__ float d_Wh[NN * FF];
__device__ float d_Hout[NN * FF];
__device__ int d_flags[NN], d_list[NN], d_count;
__device__ uint4 d_iJh[NN * 16], d_iJl[NN * 16];     // Wh fp16 hi/lo [j][f]
__device__ uint4 d_iAh[MAXT * 2048], d_iAl[MAXT * 2048];
__device__ float d_pm[MAXU * 128], d_pl[MAXU * 128];
__device__ float d_pO[(size_t)MAXU * 128 * FF];

// ---------------- helpers ----------------
__device__ __forceinline__ uint32_t smem_u32(const void* p) {
    uint32_t a;
    asm("{ .reg .u64 t; cvta.to.shared.u64 t, %1; cvt.u32.u64 %0, t; }" : "=r"(a) : "l"(p));
    return a;
}
__device__ __forceinline__ float f16r(float x) {
    return __half2float(__float2half_rn(x));
}
__device__ __forceinline__ uint32_t packhf(float lo, float hi) {
    __half2 h = __floats2half2_rn(lo, hi);
    return *(uint32_t*)&h;
}
__device__ __forceinline__ void split8(const float* v, uint4& h, uint4& l) {
    uint32_t hw[4], lw[4];
#pragma unroll
    for (int p = 0; p < 4; p++) {
        float a = v[2 * p], b = v[2 * p + 1];
        hw[p] = packhf(a, b);
        lw[p] = packhf(a - f16r(a), b - f16r(b));
    }
    h = make_uint4(hw[0], hw[1], hw[2], hw[3]);
    l = make_uint4(lw[0], lw[1], lw[2], lw[3]);
}
__device__ __forceinline__ void ldsm4(uint32_t* r, uint32_t addr) {
    asm volatile("ldmatrix.sync.aligned.m8n8.x4.shared.b16 {%0,%1,%2,%3}, [%4];"
                 : "=r"(r[0]), "=r"(r[1]), "=r"(r[2]), "=r"(r[3]) : "r"(addr));
}
__device__ __forceinline__ void ldsm4t(uint32_t* r, uint32_t addr) {
    asm volatile("ldmatrix.sync.aligned.m8n8.x4.trans.shared.b16 {%0,%1,%2,%3}, [%4];"
                 : "=r"(r[0]), "=r"(r[1]), "=r"(r[2]), "=r"(r[3]) : "r"(addr));
}
__device__ __forceinline__ void mma16816(float* d, const uint32_t* a, const uint32_t* b) {
    asm volatile("mma.sync.aligned.m16n8k16.row.col.f32.f16.f16.f32 "
                 "{%0,%1,%2,%3}, {%4,%5,%6,%7}, {%8,%9}, {%0,%1,%2,%3};"
                 : "+f"(d[0]), "+f"(d[1]), "+f"(d[2]), "+f"(d[3])
                 : "r"(a[0]), "r"(a[1]), "r"(a[2]), "r"(a[3]), "r"(b[0]), "r"(b[1]));
}
#define CPA(dst, src) \
    asm volatile("cp.async.cg.shared.global [%0], [%1], 16;" :: "r"(dst), "l"(src))
#define CPC() asm volatile("cp.async.commit_group;" ::: "memory")
#define CPW(n) asm volatile("cp.async.wait_group %0;" :: "n"(n) : "memory")

// ---------------- setup kernels ----------------
__global__ void k_init() {
    int i = blockIdx.x * blockDim.x + threadIdx.x;
    if (i < NN) d_flags[i] = 0;
    if (i == 0) d_count = 0;
}
__global__ void k_mark(const int* __restrict__ x) {
    int i = blockIdx.x * blockDim.x + threadIdx.x;
    if (i < BB) d_flags[x[i]] = 1;
}
__global__ void k_compact() {
    int i = blockIdx.x * blockDim.x + threadIdx.x;
    if (i < NN && d_flags[i]) {
        int p = atomicAdd(&d_count, 1);
        d_list[p] = i;
    }
}

// ---------------- Wh = embedding @ W  (16-row tiles, 512 CTAs) ----------------
__global__ __launch_bounds__(256) void k_whgemm(const float* __restrict__ emb,
                                                const float* __restrict__ W) {
    __shared__ float At[32][20];   // [k][m], pad 16->20
    __shared__ float Bs[32][128];  // [k][f]
    int tid = threadIdx.x, tx = tid & 31, ty = tid >> 5;
    int row0 = blockIdx.x * 16;
    float acc[2][4];
#pragma unroll
    for (int r = 0; r < 2; r++)
#pragma unroll
        for (int c = 0; c < 4; c++) acc[r][c] = 0.f;

    for (int k0 = 0; k0 < DD; k0 += 32) {
        if (tid < 128) {
            int r = tid >> 3, c4 = (tid & 7) * 4;
            float4 v = *(const float4*)&emb[(row0 + r) * DD + k0 + c4];
            At[c4 + 0][r] = v.x; At[c4 + 1][r] = v.y;
            At[c4 + 2][r] = v.z; At[c4 + 3][r] = v.w;
        }
#pragma unroll
        for (int it = 0; it < 4; it++) {
            int id = it * 256 + tid;
            int r = id >> 5, c4 = (id & 31) * 4;
            *(float4*)&Bs[r][c4] = *(const float4*)&W[(k0 + r) * FF + c4];
        }
        __syncthreads();
#pragma unroll
        for (int k = 0; k < 32; k++) {
            float2 a = *(const float2*)&At[k][2 * ty];
            float4 b = *(const float4*)&Bs[k][4 * tx];
            float av[2] = {a.x, a.y};
            float bv[4] = {b.x, b.y, b.z, b.w};
#pragma unroll
            for (int r = 0; r < 2; r++)
#pragma unroll
                for (int c = 0; c < 4; c++) acc[r][c] += av[r] * bv[c];
        }
        __syncthreads();
    }
#pragma unroll
    for (int r = 0; r < 2; r++)
        *(float4*)&d_Wh[(row0 + 2 * ty + r) * FF + 4 * tx] =
            make_float4(acc[r][0], acc[r][1], acc[r][2], acc[r][3]);
}

// ---------------- image builders ----------------
__global__ void k_imgJ() {
    int idx = blockIdx.x * 256 + threadIdx.x;
    int row = idx >> 4, c = idx & 15;
    float v[8];
    *(float4*)&v[0] = *(const float4*)&d_Wh[(size_t)row * FF + c * 8];
    *(float4*)&v[4] = *(const float4*)&d_Wh[(size_t)row * FF + c * 8 + 4];
    uint4 h, l; split8(v, h, l);
    d_iJh[idx] = h; d_iJl[idx] = l;
}
__global__ void k_imgA() {
    int idx = blockIdx.x * 256 + threadIdx.x;
    int tile = idx >> 11, gc = idx & 2047;
    int cnt = d_count;
    if (tile >= (cnt + 127) >> 7) return;
    int row = gc >> 4, c = gc & 15;
    int ridx = tile * 128 + row; if (ridx >= cnt) ridx = cnt - 1;
    const float* src = &d_Wh[(size_t)d_list[ridx] * FF + c * 8];
    float v[8];
    *(float4*)&v[0] = *(const float4*)&src[0];
    *(float4*)&v[4] = *(const float4*)&src[4];
    uint4 h, l; split8(v, h, l);
    d_iAh[idx] = h; d_iAl[idx] = l;
}

// ---------------- mma.sync fused attention (fp16 emu + fused adj pack) ----------------
__global__ __launch_bounds__(256, 1) void k_attn(const int* __restrict__ adj) {
    extern __shared__ char smc[];
    uint32_t smb = smem_u32(smc);
    const int tid = threadIdx.x, wid = tid >> 5, lane = tid & 31;
    const int g = lane >> 2, t = lane & 3;
    const int m0 = wid * 16;
    const int cnt = d_count;
    const int ntiles = (cnt + 127) >> 7;
    const int nunits = ntiles * JSPLIT;

    const int arow = m0 + (lane & 15);
    const uint32_t acolx = (lane & 16) ? 16u : 0u;
    const uint32_t abase = smb + (uint32_t)arow * 256;
    const uint32_t arot = (uint32_t)(arow & 7) * 16;

    uint32_t stoff[8];
#pragma unroll
    for (int s = 0; s < 8; s++) {
        int idx = s * 256 + tid;
        int row = idx >> 4, c = idx & 15;
        stoff[s] = (uint32_t)row * 256 + (((uint32_t)c * 16) ^ ((row & 7) * 16));
    }

    for (int u = blockIdx.x; u < nunits; u += gridDim.x) {
        const int tile = u >> 4, sl = u & 15;
        __syncthreads();

        {
            const uint4* gah = &d_iAh[tile * 2048];
            const uint4* gal = &d_iAl[tile * 2048];
            const uint4* gjh = &d_iJh[(sl * 512) * 16];
            const uint4* gjl = &d_iJl[(sl * 512) * 16];
#pragma unroll
            for (int s = 0; s < 8; s++) {
                int idx = s * 256 + tid;
                CPA(smb + SA_HI + stoff[s], gah + idx);
                CPA(smb + SA_LO + stoff[s], gal + idx);
                CPA(smb + SJB(0) + stoff[s], gjh + idx);
                CPA(smb + SJB(0) + 32768 + stoff[s], gjl + idx);
            }
            CPC();
        }

        // ---- fused adjacency pack: warp wid packs rows wid*16..wid*16+15 ----
        {
            int rbase = tile * 128 + wid * 16;
#pragma unroll 1
            for (int rr = 0; rr < 16; rr++) {
                int ridx = rbase + rr; if (ridx >= cnt) ridx = cnt - 1;
                const int* ar = adj + (size_t)d_list[ridx] * NN + sl * 512 + lane;
                int v[16];
#pragma unroll
                for (int jw = 0; jw < 16; jw++) v[jw] = ar[jw * 32];
                uint32_t mymask = 0;
#pragma unroll
                for (int jw = 0; jw < 16; jw++) {
                    uint32_t bal = __ballot_sync(0xffffffffu, v[jw] != 0);
                    if (lane == jw) mymask = bal;
                }
                if (lane < 16)
                    *(uint32_t*)(smc + SMSK + (wid * 16 + rr) * 80 + lane * 4) = mymask;
            }
        }

        float O[16][4];
#pragma unroll
        for (int ft = 0; ft < 16; ft++)
            O[ft][0] = O[ft][1] = O[ft][2] = O[ft][3] = 0.f;
        float mr0 = -1e30f, mr1 = -1e30f, l0 = 0.f, l1 = 0.f;

        uint32_t ahr[32];   // A_hi fragments, persistent for the whole unit

#pragma unroll 1
        for (int jt = 0; jt < 4; jt++) {
            const int j0 = sl * 512 + jt * 128;
            const uint32_t sjc = smb + SJB(jt & 1);

            if (jt > 0) __syncthreads();
            if (jt < 3) {
                const uint4* gjh = &d_iJh[(j0 + 128) * 16];
                const uint4* gjl = &d_iJl[(j0 + 128) * 16];
                uint32_t sjn = smb + SJB((jt + 1) & 1);
#pragma unroll
                for (int s = 0; s < 8; s++) {
                    int idx = s * 256 + tid;
                    CPA(sjn + stoff[s], gjh + idx);
                    CPA(sjn + 32768 + stoff[s], gjl + idx);
                }
                CPC();
                CPW(1);
            } else {
                CPW(0);
            }
            __syncthreads();   // covers cp.async data AND pack STS (jt==0)

            if (jt == 0) {
#pragma unroll
                for (int q = 0; q < 8; q++) {
                    uint32_t aoff = ((uint32_t)(q * 32) + acolx) ^ arot;
                    ldsm4(&ahr[4 * q], abase + SA_HI + aoff);
                }
            }

            uint4 awA = *(const uint4*)(smc + SMSK + (m0 + g) * 80 + jt * 16);
            uint4 awB = *(const uint4*)(smc + SMSK + (m0 + 8 + g) * 80 + jt * 16);
            const uint32_t* wa = &awA.x;
            const uint32_t* wb = &awB.x;

#pragma unroll
            for (int h = 0; h < 2; h++) {
                // ---- GEMM1 (3-pass fp16): S(hi.hi) + C(cross) ----
                float S[8][4], C[8][4];
#pragma unroll
                for (int nt = 0; nt < 8; nt++)
#pragma unroll
                    for (int c = 0; c < 4; c++) { S[nt][c] = 0.f; C[nt][c] = 0.f; }
#pragma unroll 2
                for (int q = 0; q < 8; q++) {
                    uint32_t al[4];
                    uint32_t aoff = ((uint32_t)(q * 32) + acolx) ^ arot;
                    ldsm4(al, abase + SA_LO + aoff);
                    const uint32_t* ah = &ahr[4 * q];
#pragma unroll
                    for (int ntp = 0; ntp < 4; ntp++) {
                        int brow = h * 64 + ntp * 16 + ((lane >> 4) & 1) * 8 + (lane & 7);
                        uint32_t boff = (uint32_t)brow * 256 +
                            (((uint32_t)(q * 32) + ((lane & 8) ? 16u : 0u)) ^ ((brow & 7) * 16));
                        uint32_t bh[4], bl[4];
                        ldsm4(bh, sjc + boff);
                        ldsm4(bl, sjc + 32768 + boff);
                        mma16816(S[2 * ntp],     ah, bh);
                        mma16816(C[2 * ntp],     ah, bl);
                        mma16816(C[2 * ntp],     al, bh);
                        mma16816(S[2 * ntp + 1], ah, bh + 2);
                        mma16816(C[2 * ntp + 1], ah, bl + 2);
                        mma16816(C[2 * ntp + 1], al, bh + 2);
                    }
                }
#pragma unroll
                for (int nt = 0; nt < 8; nt++)
#pragma unroll
                    for (int c = 0; c < 4; c++) S[nt][c] += C[nt][c];

                // ---- masked online softmax ----
                float tmA = -1e30f, tmB = -1e30f;
#pragma unroll
                for (int nt = 0; nt < 8; nt++) {
                    int bp = (h * 64 + nt * 8 + 2 * t) & 31;
                    uint32_t mA = wa[h * 2 + (nt >> 2)] >> bp;
                    uint32_t mB = wb[h * 2 + (nt >> 2)] >> bp;
                    if (mA & 1) tmA = fmaxf(tmA, S[nt][0]);
                    if (mA & 2) tmA = fmaxf(tmA, S[nt][1]);
                    if (mB & 1) tmB = fmaxf(tmB, S[nt][2]);
                    if (mB & 2) tmB = fmaxf(tmB, S[nt][3]);
                }
                tmA = fmaxf(tmA, __shfl_xor_sync(0xffffffffu, tmA, 1));
                tmA = fmaxf(tmA, __shfl_xor_sync(0xffffffffu, tmA, 2));
                tmB = fmaxf(tmB, __shfl_xor_sync(0xffffffffu, tmB, 1));
                tmB = fmaxf(tmB, __shfl_xor_sync(0xffffffffu, tmB, 2));
                float nmA = fmaxf(mr0, tmA), nmB = fmaxf(mr1, tmB);
                float scA = __expf(mr0 - nmA), scB = __expf(mr1 - nmB);
                mr0 = nmA; mr1 = nmB;
                l0 *= scA; l1 *= scB;
#pragma unroll
                for (int ft = 0; ft < 16; ft++) {
                    O[ft][0] *= scA; O[ft][1] *= scA;
                    O[ft][2] *= scB; O[ft][3] *= scB;
                }
                // ---- P = exp(S-m), fp16-packed as GEMM2 A-frags ----
                uint32_t phi[16];
#pragma unroll
                for (int nt = 0; nt < 8; nt++) {
                    int bp = (h * 64 + nt * 8 + 2 * t) & 31;
                    uint32_t mA = wa[h * 2 + (nt >> 2)] >> bp;
                    uint32_t mB = wb[h * 2 + (nt >> 2)] >> bp;
                    float p0 = (mA & 1) ? __expf(S[nt][0] - mr0) : 0.f;
                    float p1 = (mA & 2) ? __expf(S[nt][1] - mr0) : 0.f;
                    float p2 = (mB & 1) ? __expf(S[nt][2] - mr1) : 0.f;
                    float p3 = (mB & 2) ? __expf(S[nt][3] - mr1) : 0.f;
                    l0 += p0 + p1; l1 += p2 + p3;
                    int base = (nt >> 1) * 4 + (nt & 1) * 2;
                    phi[base + 0] = packhf(p0, p1);
                    phi[base + 1] = packhf(p2, p3);
                }
                // ---- GEMM2 (1-pass fp16): O += P . J_hi ----
#pragma unroll
                for (int q2 = 0; q2 < 4; q2++) {
                    int brow = h * 64 + q2 * 16 + (lane & 15);
                    uint32_t brb = (uint32_t)brow * 256;
                    uint32_t rot = (uint32_t)(brow & 7) * 16;
#pragma unroll
                    for (int ftp = 0; ftp < 8; ftp++) {
                        uint32_t boff = brb +
                            (((uint32_t)(ftp * 32) + ((lane & 16) ? 16u : 0u)) ^ rot);
                        uint32_t bh[4];
                        ldsm4t(bh, sjc + boff);
                        mma16816(O[2 * ftp],     &phi[q2 * 4], bh);
                        mma16816(O[2 * ftp + 1], &phi[q2 * 4], bh + 2);
                    }
                }
            }
        }
        // ---- epilogue ----
        l0 += __shfl_xor_sync(0xffffffffu, l0, 1);
        l0 += __shfl_xor_sync(0xffffffffu, l0, 2);
        l1 += __shfl_xor_sync(0xffffffffu, l1, 1);
        l1 += __shfl_xor_sync(0xffffffffu, l1, 2);
        int lrowA = m0 + g, lrowB = m0 + 8 + g;
        if (t == 0) {
            d_pm[u * 128 + lrowA] = mr0; d_pl[u * 128 + lrowA] = l0;
            d_pm[u * 128 + lrowB] = mr1; d_pl[u * 128 + lrowB] = l1;
        }
        size_t baseA = ((size_t)u * 128 + lrowA) * FF + 2 * t;
        size_t baseB = ((size_t)u * 128 + lrowB) * FF + 2 * t;
#pragma unroll
        for (int ft = 0; ft < 16; ft++) {
            *(float2*)&d_pO[baseA + ft * 8] = make_float2(O[ft][0], O[ft][1]);
            *(float2*)&d_pO[baseB + ft * 8] = make_float2(O[ft][2], O[ft][3]);
        }
    }
}

// ---------------- combine partials + elu + L2 normalize ----------------
__global__ __launch_bounds__(128) void k_reduce() {
    int rid = blockIdx.x, cnt = d_count;
    if (rid >= cnt) return;
    int tile = rid >> 7, m = rid & 127;
    int f = threadIdx.x;
    int base = tile * JSPLIT;
    float M = -1e30f;
#pragma unroll
    for (int s = 0; s < JSPLIT; s++) M = fmaxf(M, d_pm[(base + s) * 128 + m]);
    float L = 0.f, acc = 0.f;
#pragma unroll 4
    for (int s = 0; s < JSPLIT; s++) {
        float w = __expf(d_pm[(base + s) * 128 + m] - M);
        L += w * d_pl[(base + s) * 128 + m];
        acc += w * d_pO[((size_t)(base + s) * 128 + m) * FF + f];
    }
    float v = acc / L;
    v = (v > 0.f) ? v : expm1f(v);
    __shared__ float red[4];
    float ssq = v * v;
#pragma unroll
    for (int o = 16; o; o >>= 1) ssq += __shfl_xor_sync(0xffffffffu, ssq, o);
    if ((f & 31) == 0) red[f >> 5] = ssq;
    __syncthreads();
    ssq = red[0] + red[1] + red[2] + red[3];
    float inn = 1.f / fmaxf(sqrtf(ssq), 1e-12f);
    d_Hout[(size_t)d_list[rid] * FF + f] = v * inn;
}

__global__ void k_gather(const int* __restrict__ x, float* __restrict__ out) {
    int id = blockIdx.x * blockDim.x + threadIdx.x;
    if (id < BB * 32) {
        int b = id >> 5;
        int c4 = (id & 31) * 4;
        *(float4*)&out[b * FF + c4] = *(const float4*)&d_Hout[(size_t)x[b] * FF + c4];
    }
}

extern "C" void kernel_launch(void* const* d_in, const int* in_sizes, int n_in,
                              void* d_out, int out_size) {
    const int*   x   = (const int*)d_in[0];
    const int*   adj = (const int*)d_in[1];
    const float* emb = (const float*)d_in[2];
    const float* W   = (const float*)d_in[3];
    float* out = (float*)d_out;

    cudaFuncSetAttribute(k_attn, cudaFuncAttributeMaxDynamicSharedMemorySize, SM_TOTAL);

    k_init<<<32, 256>>>();
    k_mark<<<16, 256>>>(x);
    k_compact<<<32, 256>>>();
    k_whgemm<<<512, 256>>>(emb, W);
    k_imgJ<<<512, 256>>>();
    k_imgA<<<256, 256>>>();
    k_attn<<<148, 256, SM_TOTAL>>>(adj);
    k_reduce<<<4096, 128>>>();
    k_gather<<<512, 256>>>(x, out);
}

// round 12
// speedup vs baseline: 1.1327x; 1.1327x over previous
#include <cuda_runtime.h>
#include <cuda_fp16.h>
#include <math.h>
#include <stdint.h>

#define NN 8192
#define DD 256
#define FF 128
#define BB 4096
#define JSPLIT 16
#define MAXT 32
#define MAXU (MAXT * JSPLIT)   // 512

#define SA_HI 0
#define SA_LO 32768
#define SJB(b) (65536 + (b) * 65536)
#define SM_TOTAL 196608

// ---------------- device scratch ----------------
__device__ float d_Wh[NN * FF];
__device__ float d_Hout[NN * FF];
__device__ int d_flags[NN], d_list[NN], d_count;
__device__ uint32_t d_adjb[4096 * 256];
__device__ uint4 d_iJh[NN * 16], d_iJl[NN * 16];     // Wh fp16 hi/lo [j][f]
__device__ uint4 d_iAh[MAXT * 2048], d_iAl[MAXT * 2048];
__device__ float d_pm[MAXU * 128], d_pl[MAXU * 128];
__device__ float d_pO[(size_t)MAXU * 128 * FF];

// ---------------- helpers ----------------
__device__ __forceinline__ uint32_t smem_u32(const void* p) {
    uint32_t a;
    asm("{ .reg .u64 t; cvta.to.shared.u64 t, %1; cvt.u32.u64 %0, t; }" : "=r"(a) : "l"(p));
    return a;
}
__device__ __forceinline__ float f16r(float x) {
    return __half2float(__float2half_rn(x));
}
__device__ __forceinline__ uint32_t packhf(float lo, float hi) {
    __half2 h = __floats2half2_rn(lo, hi);
    return *(uint32_t*)&h;
}
__device__ __forceinline__ void split8(const float* v, uint4& h, uint4& l) {
    uint32_t hw[4], lw[4];
#pragma unroll
    for (int p = 0; p < 4; p++) {
        float a = v[2 * p], b = v[2 * p + 1];
        hw[p] = packhf(a, b);
        lw[p] = packhf(a - f16r(a), b - f16r(b));
    }
    h = make_uint4(hw[0], hw[1], hw[2], hw[3]);
    l = make_uint4(lw[0], lw[1], lw[2], lw[3]);
}
__device__ __forceinline__ void ldsm4(uint32_t* r, uint32_t addr) {
    asm volatile("ldmatrix.sync.aligned.m8n8.x4.shared.b16 {%0,%1,%2,%3}, [%4];"
                 : "=r"(r[0]), "=r"(r[1]), "=r"(r[2]), "=r"(r[3]) : "r"(addr));
}
__device__ __forceinline__ void ldsm4t(uint32_t* r, uint32_t addr) {
    asm volatile("ldmatrix.sync.aligned.m8n8.x4.trans.shared.b16 {%0,%1,%2,%3}, [%4];"
                 : "=r"(r[0]), "=r"(r[1]), "=r"(r[2]), "=r"(r[3]) : "r"(addr));
}
__device__ __forceinline__ void mma16816(float* d, const uint32_t* a, const uint32_t* b) {
    asm volatile("mma.sync.aligned.m16n8k16.row.col.f32.f16.f16.f32 "
                 "{%0,%1,%2,%3}, {%4,%5,%6,%7}, {%8,%9}, {%0,%1,%2,%3};"
                 : "+f"(d[0]), "+f"(d[1]), "+f"(d[2]), "+f"(d[3])
                 : "r"(a[0]), "r"(a[1]), "r"(a[2]), "r"(a[3]), "r"(b[0]), "r"(b[1]));
}
#define CPA(dst, src) \
    asm volatile("cp.async.cg.shared.global [%0], [%1], 16;" :: "r"(dst), "l"(src))
#define CPC() asm volatile("cp.async.commit_group;" ::: "memory")
#define CPW(n) asm volatile("cp.async.wait_group %0;" :: "n"(n) : "memory")

// ---------------- setup kernels ----------------
__global__ void k_init() {
    int i = blockIdx.x * blockDim.x + threadIdx.x;
    if (i < NN) d_flags[i] = 0;
    if (i == 0) d_count = 0;
}
__global__ void k_mark(const int* __restrict__ x) {
    int i = blockIdx.x * blockDim.x + threadIdx.x;
    if (i < BB) d_flags[x[i]] = 1;
}
__global__ void k_compact() {
    int i = blockIdx.x * blockDim.x + threadIdx.x;
    if (i < NN && d_flags[i]) {
        int p = atomicAdd(&d_count, 1);
        d_list[p] = i;
    }
}

// ---------------- Wh = embedding @ W (32-row tiles) + fused fp16 image split ----------------
__global__ __launch_bounds__(256) void k_whgemm(const float* __restrict__ emb,
                                                const float* __restrict__ W) {
    __shared__ float At[32][36];
    __shared__ float Bs[32][128];
    int tid = threadIdx.x, tx = tid & 31, ty = tid >> 5;
    int row0 = blockIdx.x * 32;
    float acc[4][4];
#pragma unroll
    for (int r = 0; r < 4; r++)
#pragma unroll
        for (int c = 0; c < 4; c++) acc[r][c] = 0.f;

    for (int k0 = 0; k0 < DD; k0 += 32) {
        {
            int r = tid >> 3, c4 = (tid & 7) * 4;
            float4 v = *(const float4*)&emb[(row0 + r) * DD + k0 + c4];
            At[c4 + 0][r] = v.x; At[c4 + 1][r] = v.y;
            At[c4 + 2][r] = v.z; At[c4 + 3][r] = v.w;
        }
#pragma unroll
        for (int it = 0; it < 4; it++) {
            int id = it * 256 + tid;
            int r = id >> 5, c4 = (id & 31) * 4;
            *(float4*)&Bs[r][c4] = *(const float4*)&W[(k0 + r) * FF + c4];
        }
        __syncthreads();
#pragma unroll
        for (int k = 0; k < 32; k++) {
            float4 a = *(const float4*)&At[k][4 * ty];
            float4 b = *(const float4*)&Bs[k][4 * tx];
            float av[4] = {a.x, a.y, a.z, a.w};
            float bv[4] = {b.x, b.y, b.z, b.w};
#pragma unroll
            for (int r = 0; r < 4; r++)
#pragma unroll
                for (int c = 0; c < 4; c++) acc[r][c] += av[r] * bv[c];
        }
        __syncthreads();
    }
#pragma unroll
    for (int r = 0; r < 4; r++) {
        int row = row0 + 4 * ty + r;
        float4 v = make_float4(acc[r][0], acc[r][1], acc[r][2], acc[r][3]);
        *(float4*)&d_Wh[(size_t)row * FF + 4 * tx] = v;
        // fused fp16 hi/lo image: thread pair (tx=2c, 2c+1) covers chunk c (8 cols)
        uint2 h2, l2;
        h2.x = packhf(v.x, v.y);
        h2.y = packhf(v.z, v.w);
        l2.x = packhf(v.x - f16r(v.x), v.y - f16r(v.y));
        l2.y = packhf(v.z - f16r(v.z), v.w - f16r(v.w));
        size_t woff = ((size_t)row * 16 + (tx >> 1)) * 4 + (tx & 1) * 2;
        *(uint2*)((uint32_t*)d_iJh + woff) = h2;
        *(uint2*)((uint32_t*)d_iJl + woff) = l2;
    }
}

// ---------------- image builder (A tiles, gathered) ----------------
__global__ void k_imgA() {
    int idx = blockIdx.x * 256 + threadIdx.x;
    int tile = idx >> 11, gc = idx & 2047;
    int cnt = d_count;
    if (tile >= (cnt + 127) >> 7) return;
    int row = gc >> 4, c = gc & 15;
    int ridx = tile * 128 + row; if (ridx >= cnt) ridx = cnt - 1;
    const float* src = &d_Wh[(size_t)d_list[ridx] * FF + c * 8];
    float v[8];
    *(float4*)&v[0] = *(const float4*)&src[0];
    *(float4*)&v[4] = *(const float4*)&src[4];
    uint4 h, l; split8(v, h, l);
    d_iAh[idx] = h; d_iAl[idx] = l;
}
__global__ __launch_bounds__(256) void k_adjpack(const int* __restrict__ adj) {
    int row = blockIdx.x;
    if (row >= d_count) return;
    size_t grow = (size_t)d_list[row] * NN;
    int tid = threadIdx.x, lane = tid & 31;
#pragma unroll 4
    for (int it = 0; it < 32; it++) {
        int j = it * 256 + tid;
        uint32_t bal = __ballot_sync(0xffffffffu, adj[grow + j] != 0);
        if (lane == 0) d_adjb[row * 256 + (j >> 5)] = bal;
    }
}

// ---------------- mma.sync fused attention (fp16 emu, A hi+lo in regs) ----------------
__global__ __launch_bounds__(256, 1) void k_attn() {
    extern __shared__ char smc[];
    uint32_t smb = smem_u32(smc);
    const int tid = threadIdx.x, wid = tid >> 5, lane = tid & 31;
    const int g = lane >> 2, t = lane & 3;
    const int m0 = wid * 16;
    const int cnt = d_count;
    const int ntiles = (cnt + 127) >> 7;
    const int nunits = ntiles * JSPLIT;

    const int arow = m0 + (lane & 15);
    const uint32_t acolx = (lane & 16) ? 16u : 0u;
    const uint32_t abase = smb + (uint32_t)arow * 256;
    const uint32_t arot = (uint32_t)(arow & 7) * 16;

    uint32_t stoff[8];
#pragma unroll
    for (int s = 0; s < 8; s++) {
        int idx = s * 256 + tid;
        int row = idx >> 4, c = idx & 15;
        stoff[s] = (uint32_t)row * 256 + (((uint32_t)c * 16) ^ ((row & 7) * 16));
    }

    for (int u = blockIdx.x; u < nunits; u += gridDim.x) {
        const int tile = u >> 4, sl = u & 15;
        __syncthreads();

        {
            const uint4* gah = &d_iAh[tile * 2048];
            const uint4* gal = &d_iAl[tile * 2048];
            const uint4* gjh = &d_iJh[(sl * 512) * 16];
            const uint4* gjl = &d_iJl[(sl * 512) * 16];
#pragma unroll
            for (int s = 0; s < 8; s++) {
                int idx = s * 256 + tid;
                CPA(smb + SA_HI + stoff[s], gah + idx);
                CPA(smb + SA_LO + stoff[s], gal + idx);
                CPA(smb + SJB(0) + stoff[s], gjh + idx);
                CPA(smb + SJB(0) + 32768 + stoff[s], gjl + idx);
            }
            CPC();
        }

        int rA = tile * 128 + m0 + g;
        int rB = rA + 8;
        int rAc = rA < cnt ? rA : cnt - 1;
        int rBc = rB < cnt ? rB : cnt - 1;

        float O[16][4];
#pragma unroll
        for (int ft = 0; ft < 16; ft++)
            O[ft][0] = O[ft][1] = O[ft][2] = O[ft][3] = 0.f;
        float mr0 = -1e30f, mr1 = -1e30f, l0 = 0.f, l1 = 0.f;

        uint32_t ahr[32], alr[32];   // A hi+lo fragments, persistent per unit

#pragma unroll 1
        for (int jt = 0; jt < 4; jt++) {
            const int j0 = sl * 512 + jt * 128;
            const uint32_t sjc = smb + SJB(jt & 1);

            if (jt > 0) __syncthreads();
            if (jt < 3) {
                const uint4* gjh = &d_iJh[(j0 + 128) * 16];
                const uint4* gjl = &d_iJl[(j0 + 128) * 16];
                uint32_t sjn = smb + SJB((jt + 1) & 1);
#pragma unroll
                for (int s = 0; s < 8; s++) {
                    int idx = s * 256 + tid;
                    CPA(sjn + stoff[s], gjh + idx);
                    CPA(sjn + 32768 + stoff[s], gjl + idx);
                }
                CPC();
                CPW(1);
            } else {
                CPW(0);
            }
            __syncthreads();

            if (jt == 0) {   // load persistent A fragments once
#pragma unroll
                for (int q = 0; q < 8; q++) {
                    uint32_t aoff = ((uint32_t)(q * 32) + acolx) ^ arot;
                    ldsm4(&ahr[4 * q], abase + SA_HI + aoff);
                    ldsm4(&alr[4 * q], abase + SA_LO + aoff);
                }
            }

            uint4 awA = *(const uint4*)&d_adjb[rAc * 256 + (j0 >> 5)];
            uint4 awB = *(const uint4*)&d_adjb[rBc * 256 + (j0 >> 5)];
            const uint32_t* wa = &awA.x;
            const uint32_t* wb = &awB.x;

#pragma unroll
            for (int h = 0; h < 2; h++) {
                // ---- GEMM1 (3-pass fp16): S(hi.hi) + C(cross), A from regs ----
                float S[8][4], C[8][4];
#pragma unroll
                for (int nt = 0; nt < 8; nt++)
#pragma unroll
                    for (int c = 0; c < 4; c++) { S[nt][c] = 0.f; C[nt][c] = 0.f; }
#pragma unroll 2
                for (int q = 0; q < 8; q++) {
                    const uint32_t* ah = &ahr[4 * q];
                    const uint32_t* al = &alr[4 * q];
#pragma unroll
                    for (int ntp = 0; ntp < 4; ntp++) {
                        int brow = h * 64 + ntp * 16 + ((lane >> 4) & 1) * 8 + (lane & 7);
                        uint32_t boff = (uint32_t)brow * 256 +
                            (((uint32_t)(q * 32) + ((lane & 8) ? 16u : 0u)) ^ ((brow & 7) * 16));
                        uint32_t bh[4], bl[4];
                        ldsm4(bh, sjc + boff);
                        ldsm4(bl, sjc + 32768 + boff);
                        mma16816(S[2 * ntp],     ah, bh);
                        mma16816(C[2 * ntp],     ah, bl);
                        mma16816(C[2 * ntp],     al, bh);
                        mma16816(S[2 * ntp + 1], ah, bh + 2);
                        mma16816(C[2 * ntp + 1], ah, bl + 2);
                        mma16816(C[2 * ntp + 1], al, bh + 2);
                    }
                }
#pragma unroll
                for (int nt = 0; nt < 8; nt++)
#pragma unroll
                    for (int c = 0; c < 4; c++) S[nt][c] += C[nt][c];

                // ---- masked online softmax ----
                float tmA = -1e30f, tmB = -1e30f;
#pragma unroll
                for (int nt = 0; nt < 8; nt++) {
                    int bp = (h * 64 + nt * 8 + 2 * t) & 31;
                    uint32_t mA = wa[h * 2 + (nt >> 2)] >> bp;
                    uint32_t mB = wb[h * 2 + (nt >> 2)] >> bp;
                    if (mA & 1) tmA = fmaxf(tmA, S[nt][0]);
                    if (mA & 2) tmA = fmaxf(tmA, S[nt][1]);
                    if (mB & 1) tmB = fmaxf(tmB, S[nt][2]);
                    if (mB & 2) tmB = fmaxf(tmB, S[nt][3]);
                }
                tmA = fmaxf(tmA, __shfl_xor_sync(0xffffffffu, tmA, 1));
                tmA = fmaxf(tmA, __shfl_xor_sync(0xffffffffu, tmA, 2));
                tmB = fmaxf(tmB, __shfl_xor_sync(0xffffffffu, tmB, 1));
                tmB = fmaxf(tmB, __shfl_xor_sync(0xffffffffu, tmB, 2));
                float nmA = fmaxf(mr0, tmA), nmB = fmaxf(mr1, tmB);
                float scA = __expf(mr0 - nmA), scB = __expf(mr1 - nmB);
                mr0 = nmA; mr1 = nmB;
                l0 *= scA; l1 *= scB;
#pragma unroll
                for (int ft = 0; ft < 16; ft++) {
                    O[ft][0] *= scA; O[ft][1] *= scA;
                    O[ft][2] *= scB; O[ft][3] *= scB;
                }
                // ---- P = exp(S-m), fp16-packed as GEMM2 A-frags ----
                uint32_t phi[16];
#pragma unroll
                for (int nt = 0; nt < 8; nt++) {
                    int bp = (h * 64 + nt * 8 + 2 * t) & 31;
                    uint32_t mA = wa[h * 2 + (nt >> 2)] >> bp;
                    uint32_t mB = wb[h * 2 + (nt >> 2)] >> bp;
                    float p0 = (mA & 1) ? __expf(S[nt][0] - mr0) : 0.f;
                    float p1 = (mA & 2) ? __expf(S[nt][1] - mr0) : 0.f;
                    float p2 = (mB & 1) ? __expf(S[nt][2] - mr1) : 0.f;
                    float p3 = (mB & 2) ? __expf(S[nt][3] - mr1) : 0.f;
                    l0 += p0 + p1; l1 += p2 + p3;
                    int base = (nt >> 1) * 4 + (nt & 1) * 2;
                    phi[base + 0] = packhf(p0, p1);
                    phi[base + 1] = packhf(p2, p3);
                }
                // ---- GEMM2 (1-pass fp16): O += P . J_hi ----
#pragma unroll
                for (int q2 = 0; q2 < 4; q2++) {
                    int brow = h * 64 + q2 * 16 + (lane & 15);
                    uint32_t brb = (uint32_t)brow * 256;
                    uint32_t rot = (uint32_t)(brow & 7) * 16;
#pragma unroll
                    for (int ftp = 0; ftp < 8; ftp++) {
                        uint32_t boff = brb +
                            (((uint32_t)(ftp * 32) + ((lane & 16) ? 16u : 0u)) ^ rot);
                        uint32_t bh[4];
                        ldsm4t(bh, sjc + boff);
                        mma16816(O[2 * ftp],     &phi[q2 * 4], bh);
                        mma16816(O[2 * ftp + 1], &phi[q2 * 4], bh + 2);
                    }
                }
            }
        }
        // ---- epilogue ----
        l0 += __shfl_xor_sync(0xffffffffu, l0, 1);
        l0 += __shfl_xor_sync(0xffffffffu, l0, 2);
        l1 += __shfl_xor_sync(0xffffffffu, l1, 1);
        l1 += __shfl_xor_sync(0xffffffffu, l1, 2);
        int lrowA = m0 + g, lrowB = m0 + 8 + g;
        if (t == 0) {
            d_pm[u * 128 + lrowA] = mr0; d_pl[u * 128 + lrowA] = l0;
            d_pm[u * 128 + lrowB] = mr1; d_pl[u * 128 + lrowB] = l1;
        }
        size_t baseA = ((size_t)u * 128 + lrowA) * FF + 2 * t;
        size_t baseB = ((size_t)u * 128 + lrowB) * FF + 2 * t;
#pragma unroll
        for (int ft = 0; ft < 16; ft++) {
            *(float2*)&d_pO[baseA + ft * 8] = make_float2(O[ft][0], O[ft][1]);
            *(float2*)&d_pO[baseB + ft * 8] = make_float2(O[ft][2], O[ft][3]);
        }
    }
}

// ---------------- combine partials + elu + L2 normalize ----------------
__global__ __launch_bounds__(128) void k_reduce() {
    int rid = blockIdx.x, cnt = d_count;
    if (rid >= cnt) return;
    int tile = rid >> 7, m = rid & 127;
    int f = threadIdx.x;
    int base = tile * JSPLIT;
    float M = -1e30f;
#pragma unroll
    for (int s = 0; s < JSPLIT; s++) M = fmaxf(M, d_pm[(base + s) * 128 + m]);
    float L = 0.f, acc = 0.f;
#pragma unroll 4
    for (int s = 0; s < JSPLIT; s++) {
        float w = __expf(d_pm[(base + s) * 128 + m] - M);
        L += w * d_pl[(base + s) * 128 + m];
        acc += w * d_pO[((size_t)(base + s) * 128 + m) * FF + f];
    }
    float v = acc / L;
    v = (v > 0.f) ? v : expm1f(v);
    __shared__ float red[4];
    float ssq = v * v;
#pragma unroll
    for (int o = 16; o; o >>= 1) ssq += __shfl_xor_sync(0xffffffffu, ssq, o);
    if ((f & 31) == 0) red[f >> 5] = ssq;
    __syncthreads();
    ssq = red[0] + red[1] + red[2] + red[3];
    float inn = 1.f / fmaxf(sqrtf(ssq), 1e-12f);
    d_Hout[(size_t)d_list[rid] * FF + f] = v * inn;
}

__global__ void k_gather(const int* __restrict__ x, float* __restrict__ out) {
    int id = blockIdx.x * blockDim.x + threadIdx.x;
    if (id < BB * 32) {
        int b = id >> 5;
        int c4 = (id & 31) * 4;
        *(float4*)&out[b * FF + c4] = *(const float4*)&d_Hout[(size_t)x[b] * FF + c4];
    }
}

extern "C" void kernel_launch(void* const* d_in, const int* in_sizes, int n_in,
                              void* d_out, int out_size) {
    const int*   x   = (const int*)d_in[0];
    const int*   adj = (const int*)d_in[1];
    const float* emb = (const float*)d_in[2];
    const float* W   = (const float*)d_in[3];
    float* out = (float*)d_out;

    cudaFuncSetAttribute(k_attn, cudaFuncAttributeMaxDynamicSharedMemorySize, SM_TOTAL);

    k_init<<<32, 256>>>();
    k_mark<<<16, 256>>>(x);
    k_compact<<<32, 256>>>();
    k_whgemm<<<256, 256>>>(emb, W);
    k_adjpack<<<4096, 256>>>(adj);
    k_imgA<<<256, 256>>>();
    k_attn<<<148, 256, SM_TOTAL>>>();
    k_reduce<<<4096, 128>>>();
    k_gather<<<512, 256>>>(x, out);
}

// round 13
// speedup vs baseline: 1.1615x; 1.0254x over previous
#include <cuda_runtime.h>
#include <cuda_fp16.h>
#include <math.h>
#include <stdint.h>

#define NN 8192
#define DD 256
#define FF 128
#define BB 4096
#define JSPLIT 16
#define MAXT 32
#define MAXU (MAXT * JSPLIT)   // 512

#define SA_HI 0
#define SA_LO 32768
#define SJB(b) (65536 + (b) * 65536)
#define SM_TOTAL 196608

// ---------------- device scratch ----------------
__device__ float d_Wh[NN * FF];
__device__ float d_Hout[NN * FF];
__device__ int d_flags[NN], d_list[NN], d_count;
__device__ uint32_t d_adjb[4096 * 256];
__device__ uint4 d_iJh[NN * 16], d_iJl[NN * 16];     // Wh fp16 hi/lo [j][f]
__device__ uint4 d_iAh[MAXT * 2048], d_iAl[MAXT * 2048];
__device__ float d_pm[MAXU * 128], d_pl[MAXU * 128];
__device__ float d_pO[(size_t)MAXU * 128 * FF];

// ---------------- helpers ----------------
__device__ __forceinline__ uint32_t smem_u32(const void* p) {
    uint32_t a;
    asm("{ .reg .u64 t; cvta.to.shared.u64 t, %1; cvt.u32.u64 %0, t; }" : "=r"(a) : "l"(p));
    return a;
}
__device__ __forceinline__ float f16r(float x) {
    return __half2float(__float2half_rn(x));
}
__device__ __forceinline__ uint32_t packhf(float lo, float hi) {
    __half2 h = __floats2half2_rn(lo, hi);
    return *(uint32_t*)&h;
}
__device__ __forceinline__ void split8(const float* v, uint4& h, uint4& l) {
    uint32_t hw[4], lw[4];
#pragma unroll
    for (int p = 0; p < 4; p++) {
        float a = v[2 * p], b = v[2 * p + 1];
        hw[p] = packhf(a, b);
        lw[p] = packhf(a - f16r(a), b - f16r(b));
    }
    h = make_uint4(hw[0], hw[1], hw[2], hw[3]);
    l = make_uint4(lw[0], lw[1], lw[2], lw[3]);
}
__device__ __forceinline__ void ldsm4(uint32_t* r, uint32_t addr) {
    asm volatile("ldmatrix.sync.aligned.m8n8.x4.shared.b16 {%0,%1,%2,%3}, [%4];"
                 : "=r"(r[0]), "=r"(r[1]), "=r"(r[2]), "=r"(r[3]) : "r"(addr));
}
__device__ __forceinline__ void ldsm4t(uint32_t* r, uint32_t addr) {
    asm volatile("ldmatrix.sync.aligned.m8n8.x4.trans.shared.b16 {%0,%1,%2,%3}, [%4];"
                 : "=r"(r[0]), "=r"(r[1]), "=r"(r[2]), "=r"(r[3]) : "r"(addr));
}
__device__ __forceinline__ void mma16816(float* d, const uint32_t* a, const uint32_t* b) {
    asm volatile("mma.sync.aligned.m16n8k16.row.col.f32.f16.f16.f32 "
                 "{%0,%1,%2,%3}, {%4,%5,%6,%7}, {%8,%9}, {%0,%1,%2,%3};"
                 : "+f"(d[0]), "+f"(d[1]), "+f"(d[2]), "+f"(d[3])
                 : "r"(a[0]), "r"(a[1]), "r"(a[2]), "r"(a[3]), "r"(b[0]), "r"(b[1]));
}
#define CPA(dst, src) \
    asm volatile("cp.async.cg.shared.global [%0], [%1], 16;" :: "r"(dst), "l"(src))
#define CPC() asm volatile("cp.async.commit_group;" ::: "memory")
#define CPW(n) asm volatile("cp.async.wait_group %0;" :: "n"(n) : "memory")

// ---------------- setup kernels ----------------
__global__ void k_init() {
    int i = blockIdx.x * blockDim.x + threadIdx.x;
    if (i < NN) d_flags[i] = 0;
    if (i == 0) d_count = 0;
}
__global__ void k_mark(const int* __restrict__ x) {
    int i = blockIdx.x * blockDim.x + threadIdx.x;
    if (i < BB) d_flags[x[i]] = 1;
}
__global__ void k_compact() {
    int i = blockIdx.x * blockDim.x + threadIdx.x;
    if (i < NN && d_flags[i]) {
        int p = atomicAdd(&d_count, 1);
        d_list[p] = i;
    }
}

// ---------------- merged: whgemm (+fused fp16 image) | adjpack ----------------
// blocks [0,256): Wh = emb @ W, 32-row tiles, emits d_Wh + d_iJh/d_iJl
// blocks [256, 256+4096): adjacency bit-pack for compacted rows
__global__ __launch_bounds__(256) void k_wh_adj(const float* __restrict__ emb,
                                                const float* __restrict__ W,
                                                const int* __restrict__ adj) {
    int tid = threadIdx.x;
    if (blockIdx.x >= 256) {
        int row = blockIdx.x - 256;
        if (row >= d_count) return;
        size_t grow = (size_t)d_list[row] * NN;
        int lane = tid & 31;
#pragma unroll 4
        for (int it = 0; it < 32; it++) {
            int j = it * 256 + tid;
            uint32_t bal = __ballot_sync(0xffffffffu, adj[grow + j] != 0);
            if (lane == 0) d_adjb[row * 256 + (j >> 5)] = bal;
        }
        return;
    }

    __shared__ float At[32][36];
    __shared__ float Bs[32][128];
    int tx = tid & 31, ty = tid >> 5;
    int row0 = blockIdx.x * 32;
    float acc[4][4];
#pragma unroll
    for (int r = 0; r < 4; r++)
#pragma unroll
        for (int c = 0; c < 4; c++) acc[r][c] = 0.f;

    for (int k0 = 0; k0 < DD; k0 += 32) {
        {
            int r = tid >> 3, c4 = (tid & 7) * 4;
            float4 v = *(const float4*)&emb[(row0 + r) * DD + k0 + c4];
            At[c4 + 0][r] = v.x; At[c4 + 1][r] = v.y;
            At[c4 + 2][r] = v.z; At[c4 + 3][r] = v.w;
        }
#pragma unroll
        for (int it = 0; it < 4; it++) {
            int id = it * 256 + tid;
            int r = id >> 5, c4 = (id & 31) * 4;
            *(float4*)&Bs[r][c4] = *(const float4*)&W[(k0 + r) * FF + c4];
        }
        __syncthreads();
#pragma unroll
        for (int k = 0; k < 32; k++) {
            float4 a = *(const float4*)&At[k][4 * ty];
            float4 b = *(const float4*)&Bs[k][4 * tx];
            float av[4] = {a.x, a.y, a.z, a.w};
            float bv[4] = {b.x, b.y, b.z, b.w};
#pragma unroll
            for (int r = 0; r < 4; r++)
#pragma unroll
                for (int c = 0; c < 4; c++) acc[r][c] += av[r] * bv[c];
        }
        __syncthreads();
    }
#pragma unroll
    for (int r = 0; r < 4; r++) {
        int row = row0 + 4 * ty + r;
        float4 v = make_float4(acc[r][0], acc[r][1], acc[r][2], acc[r][3]);
        *(float4*)&d_Wh[(size_t)row * FF + 4 * tx] = v;
        uint2 h2, l2;
        h2.x = packhf(v.x, v.y);
        h2.y = packhf(v.z, v.w);
        l2.x = packhf(v.x - f16r(v.x), v.y - f16r(v.y));
        l2.y = packhf(v.z - f16r(v.z), v.w - f16r(v.w));
        size_t woff = ((size_t)row * 16 + (tx >> 1)) * 4 + (tx & 1) * 2;
        *(uint2*)((uint32_t*)d_iJh + woff) = h2;
        *(uint2*)((uint32_t*)d_iJl + woff) = l2;
    }
}

// ---------------- image builder (A tiles, gathered) ----------------
__global__ void k_imgA() {
    int idx = blockIdx.x * 256 + threadIdx.x;
    int tile = idx >> 11, gc = idx & 2047;
    int cnt = d_count;
    if (tile >= (cnt + 127) >> 7) return;
    int row = gc >> 4, c = gc & 15;
    int ridx = tile * 128 + row; if (ridx >= cnt) ridx = cnt - 1;
    const float* src = &d_Wh[(size_t)d_list[ridx] * FF + c * 8];
    float v[8];
    *(float4*)&v[0] = *(const float4*)&src[0];
    *(float4*)&v[4] = *(const float4*)&src[4];
    uint4 h, l; split8(v, h, l);
    d_iAh[idx] = h; d_iAl[idx] = l;
}

// ---------------- mma.sync fused attention (fp16 emu, A_hi in regs) ----------------
__global__ __launch_bounds__(256, 1) void k_attn() {
    extern __shared__ char smc[];
    uint32_t smb = smem_u32(smc);
    const int tid = threadIdx.x, wid = tid >> 5, lane = tid & 31;
    const int g = lane >> 2, t = lane & 3;
    const int m0 = wid * 16;
    const int cnt = d_count;
    const int ntiles = (cnt + 127) >> 7;
    const int nunits = ntiles * JSPLIT;

    const int arow = m0 + (lane & 15);
    const uint32_t acolx = (lane & 16) ? 16u : 0u;
    const uint32_t abase = smb + (uint32_t)arow * 256;
    const uint32_t arot = (uint32_t)(arow & 7) * 16;

    uint32_t stoff[8];
#pragma unroll
    for (int s = 0; s < 8; s++) {
        int idx = s * 256 + tid;
        int row = idx >> 4, c = idx & 15;
        stoff[s] = (uint32_t)row * 256 + (((uint32_t)c * 16) ^ ((row & 7) * 16));
    }

    for (int u = blockIdx.x; u < nunits; u += gridDim.x) {
        const int tile = u >> 4, sl = u & 15;
        __syncthreads();

        {
            const uint4* gah = &d_iAh[tile * 2048];
            const uint4* gal = &d_iAl[tile * 2048];
            const uint4* gjh = &d_iJh[(sl * 512) * 16];
            const uint4* gjl = &d_iJl[(sl * 512) * 16];
#pragma unroll
            for (int s = 0; s < 8; s++) {
                int idx = s * 256 + tid;
                CPA(smb + SA_HI + stoff[s], gah + idx);
                CPA(smb + SA_LO + stoff[s], gal + idx);
                CPA(smb + SJB(0) + stoff[s], gjh + idx);
                CPA(smb + SJB(0) + 32768 + stoff[s], gjl + idx);
            }
            CPC();
        }

        int rA = tile * 128 + m0 + g;
        int rB = rA + 8;
        int rAc = rA < cnt ? rA : cnt - 1;
        int rBc = rB < cnt ? rB : cnt - 1;

        float O[16][4];
#pragma unroll
        for (int ft = 0; ft < 16; ft++)
            O[ft][0] = O[ft][1] = O[ft][2] = O[ft][3] = 0.f;
        float mr0 = -1e30f, mr1 = -1e30f, l0 = 0.f, l1 = 0.f;

        uint32_t ahr[32];   // A_hi fragments, persistent for the whole unit

#pragma unroll 1
        for (int jt = 0; jt < 4; jt++) {
            const int j0 = sl * 512 + jt * 128;
            const uint32_t sjc = smb + SJB(jt & 1);

            if (jt > 0) __syncthreads();
            if (jt < 3) {
                const uint4* gjh = &d_iJh[(j0 + 128) * 16];
                const uint4* gjl = &d_iJl[(j0 + 128) * 16];
                uint32_t sjn = smb + SJB((jt + 1) & 1);
#pragma unroll
                for (int s = 0; s < 8; s++) {
                    int idx = s * 256 + tid;
                    CPA(sjn + stoff[s], gjh + idx);
                    CPA(sjn + 32768 + stoff[s], gjl + idx);
                }
                CPC();
                CPW(1);
            } else {
                CPW(0);
            }
            __syncthreads();

            if (jt == 0) {
#pragma unroll
                for (int q = 0; q < 8; q++) {
                    uint32_t aoff = ((uint32_t)(q * 32) + acolx) ^ arot;
                    ldsm4(&ahr[4 * q], abase + SA_HI + aoff);
                }
            }

            uint4 awA = *(const uint4*)&d_adjb[rAc * 256 + (j0 >> 5)];
            uint4 awB = *(const uint4*)&d_adjb[rBc * 256 + (j0 >> 5)];
            const uint32_t* wa = &awA.x;
            const uint32_t* wb = &awB.x;

#pragma unroll
            for (int h = 0; h < 2; h++) {
                // ---- GEMM1 (3-pass fp16): S(hi.hi) + C(cross) ----
                float S[8][4], C[8][4];
#pragma unroll
                for (int nt = 0; nt < 8; nt++)
#pragma unroll
                    for (int c = 0; c < 4; c++) { S[nt][c] = 0.f; C[nt][c] = 0.f; }
#pragma unroll 2
                for (int q = 0; q < 8; q++) {
                    uint32_t al[4];
                    uint32_t aoff = ((uint32_t)(q * 32) + acolx) ^ arot;
                    ldsm4(al, abase + SA_LO + aoff);
                    const uint32_t* ah = &ahr[4 * q];
#pragma unroll
                    for (int ntp = 0; ntp < 4; ntp++) {
                        int brow = h * 64 + ntp * 16 + ((lane >> 4) & 1) * 8 + (lane & 7);
                        uint32_t boff = (uint32_t)brow * 256 +
                            (((uint32_t)(q * 32) + ((lane & 8) ? 16u : 0u)) ^ ((brow & 7) * 16));
                        uint32_t bh[4], bl[4];
                        ldsm4(bh, sjc + boff);
                        ldsm4(bl, sjc + 32768 + boff);
                        mma16816(S[2 * ntp],     ah, bh);
                        mma16816(C[2 * ntp],     ah, bl);
                        mma16816(C[2 * ntp],     al, bh);
                        mma16816(S[2 * ntp + 1], ah, bh + 2);
                        mma16816(C[2 * ntp + 1], ah, bl + 2);
                        mma16816(C[2 * ntp + 1], al, bh + 2);
                    }
                }
#pragma unroll
                for (int nt = 0; nt < 8; nt++)
#pragma unroll
                    for (int c = 0; c < 4; c++) S[nt][c] += C[nt][c];

                // ---- masked online softmax ----
                float tmA = -1e30f, tmB = -1e30f;
#pragma unroll
                for (int nt = 0; nt < 8; nt++) {
                    int bp = (h * 64 + nt * 8 + 2 * t) & 31;
                    uint32_t mA = wa[h * 2 + (nt >> 2)] >> bp;
                    uint32_t mB = wb[h * 2 + (nt >> 2)] >> bp;
                    if (mA & 1) tmA = fmaxf(tmA, S[nt][0]);
                    if (mA & 2) tmA = fmaxf(tmA, S[nt][1]);
                    if (mB & 1) tmB = fmaxf(tmB, S[nt][2]);
                    if (mB & 2) tmB = fmaxf(tmB, S[nt][3]);
                }
                tmA = fmaxf(tmA, __shfl_xor_sync(0xffffffffu, tmA, 1));
                tmA = fmaxf(tmA, __shfl_xor_sync(0xffffffffu, tmA, 2));
                tmB = fmaxf(tmB, __shfl_xor_sync(0xffffffffu, tmB, 1));
                tmB = fmaxf(tmB, __shfl_xor_sync(0xffffffffu, tmB, 2));
                float nmA = fmaxf(mr0, tmA), nmB = fmaxf(mr1, tmB);
                float scA = __expf(mr0 - nmA), scB = __expf(mr1 - nmB);
                mr0 = nmA; mr1 = nmB;
                l0 *= scA; l1 *= scB;
#pragma unroll
                for (int ft = 0; ft < 16; ft++) {
                    O[ft][0] *= scA; O[ft][1] *= scA;
                    O[ft][2] *= scB; O[ft][3] *= scB;
                }
                // ---- P = exp(S-m), fp16-packed as GEMM2 A-frags ----
                uint32_t phi[16];
#pragma unroll
                for (int nt = 0; nt < 8; nt++) {
                    int bp = (h * 64 + nt * 8 + 2 * t) & 31;
                    uint32_t mA = wa[h * 2 + (nt >> 2)] >> bp;
                    uint32_t mB = wb[h * 2 + (nt >> 2)] >> bp;
                    float p0 = (mA & 1) ? __expf(S[nt][0] - mr0) : 0.f;
                    float p1 = (mA & 2) ? __expf(S[nt][1] - mr0) : 0.f;
                    float p2 = (mB & 1) ? __expf(S[nt][2] - mr1) : 0.f;
                    float p3 = (mB & 2) ? __expf(S[nt][3] - mr1) : 0.f;
                    l0 += p0 + p1; l1 += p2 + p3;
                    int base = (nt >> 1) * 4 + (nt & 1) * 2;
                    phi[base + 0] = packhf(p0, p1);
                    phi[base + 1] = packhf(p2, p3);
                }
                // ---- GEMM2 (1-pass fp16): O += P . J_hi ----
#pragma unroll
                for (int q2 = 0; q2 < 4; q2++) {
                    int brow = h * 64 + q2 * 16 + (lane & 15);
                    uint32_t brb = (uint32_t)brow * 256;
                    uint32_t rot = (uint32_t)(brow & 7) * 16;
#pragma unroll
                    for (int ftp = 0; ftp < 8; ftp++) {
                        uint32_t boff = brb +
                            (((uint32_t)(ftp * 32) + ((lane & 16) ? 16u : 0u)) ^ rot);
                        uint32_t bh[4];
                        ldsm4t(bh, sjc + boff);
                        mma16816(O[2 * ftp],     &phi[q2 * 4], bh);
                        mma16816(O[2 * ftp + 1], &phi[q2 * 4], bh + 2);
                    }
                }
            }
        }
        // ---- epilogue ----
        l0 += __shfl_xor_sync(0xffffffffu, l0, 1);
        l0 += __shfl_xor_sync(0xffffffffu, l0, 2);
        l1 += __shfl_xor_sync(0xffffffffu, l1, 1);
        l1 += __shfl_xor_sync(0xffffffffu, l1, 2);
        int lrowA = m0 + g, lrowB = m0 + 8 + g;
        if (t == 0) {
            d_pm[u * 128 + lrowA] = mr0; d_pl[u * 128 + lrowA] = l0;
            d_pm[u * 128 + lrowB] = mr1; d_pl[u * 128 + lrowB] = l1;
        }
        size_t baseA = ((size_t)u * 128 + lrowA) * FF + 2 * t;
        size_t baseB = ((size_t)u * 128 + lrowB) * FF + 2 * t;
#pragma unroll
        for (int ft = 0; ft < 16; ft++) {
            *(float2*)&d_pO[baseA + ft * 8] = make_float2(O[ft][0], O[ft][1]);
            *(float2*)&d_pO[baseB + ft * 8] = make_float2(O[ft][2], O[ft][3]);
        }
    }
}

// ---------------- combine partials + elu + L2 normalize ----------------
__global__ __launch_bounds__(128) void k_reduce() {
    int rid = blockIdx.x, cnt = d_count;
    if (rid >= cnt) return;
    int tile = rid >> 7, m = rid & 127;
    int f = threadIdx.x;
    int base = tile * JSPLIT;
    float M = -1e30f;
#pragma unroll
    for (int s = 0; s < JSPLIT; s++) M = fmaxf(M, d_pm[(base + s) * 128 + m]);
    float L = 0.f, acc = 0.f;
#pragma unroll 4
    for (int s = 0; s < JSPLIT; s++) {
        float w = __expf(d_pm[(base + s) * 128 + m] - M);
        L += w * d_pl[(base + s) * 128 + m];
        acc += w * d_pO[((size_t)(base + s) * 128 + m) * FF + f];
    }
    float v = acc / L;
    v = (v > 0.f) ? v : expm1f(v);
    __shared__ float red[4];
    float ssq = v * v;
#pragma unroll
    for (int o = 16; o; o >>= 1) ssq += __shfl_xor_sync(0xffffffffu, ssq, o);
    if ((f & 31) == 0) red[f >> 5] = ssq;
    __syncthreads();
    ssq = red[0] + red[1] + red[2] + red[3];
    float inn = 1.f / fmaxf(sqrtf(ssq), 1e-12f);
    d_Hout[(size_t)d_list[rid] * FF + f] = v * inn;
}

__global__ void k_gather(const int* __restrict__ x, float* __restrict__ out) {
    int id = blockIdx.x * blockDim.x + threadIdx.x;
    if (id < BB * 32) {
        int b = id >> 5;
        int c4 = (id & 31) * 4;
        *(float4*)&out[b * FF + c4] = *(const float4*)&d_Hout[(size_t)x[b] * FF + c4];
    }
}

extern "C" void kernel_launch(void* const* d_in, const int* in_sizes, int n_in,
                              void* d_out, int out_size) {
    const int*   x   = (const int*)d_in[0];
    const int*   adj = (const int*)d_in[1];
    const float* emb = (const float*)d_in[2];
    const float* W   = (const float*)d_in[3];
    float* out = (float*)d_out;

    cudaFuncSetAttribute(k_attn, cudaFuncAttributeMaxDynamicSharedMemorySize, SM_TOTAL);

    k_init<<<32, 256>>>();
    k_mark<<<16, 256>>>(x);
    k_compact<<<32, 256>>>();
    k_wh_adj<<<256 + 4096, 256>>>(emb, W, adj);
    k_imgA<<<256, 256>>>();
    k_attn<<<148, 256, SM_TOTAL>>>();
    k_reduce<<<4096, 128>>>();
    k_gather<<<512, 256>>>(x, out);
}

// round 14
// speedup vs baseline: 1.2951x; 1.1150x over previous
#include <cuda_runtime.h>
#include <cuda_fp16.h>
#include <math.h>
#include <stdint.h>

#define NN 8192
#define DD 256
#define FF 128
#define BB 4096
#define JSPLIT 16
#define MAXT 32
#define MAXU (MAXT * JSPLIT)   // 512

#define SA_HI 0
#define SA_LO 32768
#define SJB(b) (65536 + (b) * 65536)
#define SM_TOTAL 196608

// ---------------- device scratch ----------------
__device__ float d_Wh[NN * FF];
__device__ float d_Hout[NN * FF];
__device__ int d_flags[NN], d_list[NN], d_count;
__device__ uint32_t d_adjb[4096 * 256];
__device__ uint4 d_iJh[NN * 16], d_iJl[NN * 16];     // Wh fp16 hi/lo [j][f]
__device__ uint4 d_iAh[MAXT * 2048], d_iAl[MAXT * 2048];
__device__ float d_pm[MAXU * 128], d_pl[MAXU * 128];
__device__ float d_pO[(size_t)MAXU * 128 * FF];

// ---------------- helpers ----------------
__device__ __forceinline__ uint32_t smem_u32(const void* p) {
    uint32_t a;
    asm("{ .reg .u64 t; cvta.to.shared.u64 t, %1; cvt.u32.u64 %0, t; }" : "=r"(a) : "l"(p));
    return a;
}
__device__ __forceinline__ float f16r(float x) {
    return __half2float(__float2half_rn(x));
}
__device__ __forceinline__ uint32_t packhf(float lo, float hi) {
    __half2 h = __floats2half2_rn(lo, hi);
    return *(uint32_t*)&h;
}
__device__ __forceinline__ void split8(const float* v, uint4& h, uint4& l) {
    uint32_t hw[4], lw[4];
#pragma unroll
    for (int p = 0; p < 4; p++) {
        float a = v[2 * p], b = v[2 * p + 1];
        hw[p] = packhf(a, b);
        lw[p] = packhf(a - f16r(a), b - f16r(b));
    }
    h = make_uint4(hw[0], hw[1], hw[2], hw[3]);
    l = make_uint4(lw[0], lw[1], lw[2], lw[3]);
}
__device__ __forceinline__ void ldsm4(uint32_t* r, uint32_t addr) {
    asm volatile("ldmatrix.sync.aligned.m8n8.x4.shared.b16 {%0,%1,%2,%3}, [%4];"
                 : "=r"(r[0]), "=r"(r[1]), "=r"(r[2]), "=r"(r[3]) : "r"(addr));
}
__device__ __forceinline__ void ldsm4t(uint32_t* r, uint32_t addr) {
    asm volatile("ldmatrix.sync.aligned.m8n8.x4.trans.shared.b16 {%0,%1,%2,%3}, [%4];"
                 : "=r"(r[0]), "=r"(r[1]), "=r"(r[2]), "=r"(r[3]) : "r"(addr));
}
__device__ __forceinline__ void mma16816(float* d, const uint32_t* a, const uint32_t* b) {
    asm volatile("mma.sync.aligned.m16n8k16.row.col.f32.f16.f16.f32 "
                 "{%0,%1,%2,%3}, {%4,%5,%6,%7}, {%8,%9}, {%0,%1,%2,%3};"
                 : "+f"(d[0]), "+f"(d[1]), "+f"(d[2]), "+f"(d[3])
                 : "r"(a[0]), "r"(a[1]), "r"(a[2]), "r"(a[3]), "r"(b[0]), "r"(b[1]));
}
#define CPA(dst, src) \
    asm volatile("cp.async.cg.shared.global [%0], [%1], 16;" :: "r"(dst), "l"(src))
#define CPC() asm volatile("cp.async.commit_group;" ::: "memory")
#define CPW(n) asm volatile("cp.async.wait_group %0;" :: "n"(n) : "memory")

// ---------------- setup kernels ----------------
__global__ void k_init() {
    int i = blockIdx.x * blockDim.x + threadIdx.x;
    if (i < NN) d_flags[i] = 0;
    if (i == 0) d_count = 0;
}
__global__ void k_mark(const int* __restrict__ x) {
    int i = blockIdx.x * blockDim.x + threadIdx.x;
    if (i < BB) d_flags[x[i]] = 1;
}
__global__ void k_compact() {
    int i = blockIdx.x * blockDim.x + threadIdx.x;
    if (i < NN && d_flags[i]) {
        int p = atomicAdd(&d_count, 1);
        d_list[p] = i;
    }
}

// ---------------- merged: whgemm (+fused fp16 image) | adjpack (int4 + shfl tree) ----------------
// blocks [0,256): Wh = emb @ W, 32-row tiles, emits d_Wh + d_iJh/d_iJl
// blocks [256, 256+4096): adjacency bit-pack for compacted rows
__global__ __launch_bounds__(256) void k_wh_adj(const float* __restrict__ emb,
                                                const float* __restrict__ W,
                                                const int* __restrict__ adj) {
    int tid = threadIdx.x;
    if (blockIdx.x >= 256) {
        int row = blockIdx.x - 256;
        if (row >= d_count) return;
        const int4* ar = (const int4*)(adj + (size_t)d_list[row] * NN);
        int lane = tid & 31;
#pragma unroll
        for (int it = 0; it < 8; it++) {
            int idx = it * 256 + tid;              // int4 index: j = idx*4 .. idx*4+3
            int4 v = ar[idx];
            uint32_t nib = (uint32_t)(v.x != 0) | ((uint32_t)(v.y != 0) << 1) |
                           ((uint32_t)(v.z != 0) << 2) | ((uint32_t)(v.w != 0) << 3);
            nib |= __shfl_down_sync(0xffffffffu, nib, 1) << 4;
            nib |= __shfl_down_sync(0xffffffffu, nib, 2) << 8;
            nib |= __shfl_down_sync(0xffffffffu, nib, 4) << 16;
            if ((lane & 7) == 0)
                d_adjb[row * 256 + (idx >> 3)] = nib;
        }
        return;
    }

    __shared__ float At[32][36];
    __shared__ float Bs[32][128];
    int tx = tid & 31, ty = tid >> 5;
    int row0 = blockIdx.x * 32;
    float acc[4][4];
#pragma unroll
    for (int r = 0; r < 4; r++)
#pragma unroll
        for (int c = 0; c < 4; c++) acc[r][c] = 0.f;

    for (int k0 = 0; k0 < DD; k0 += 32) {
        {
            int r = tid >> 3, c4 = (tid & 7) * 4;
            float4 v = *(const float4*)&emb[(row0 + r) * DD + k0 + c4];
            At[c4 + 0][r] = v.x; At[c4 + 1][r] = v.y;
            At[c4 + 2][r] = v.z; At[c4 + 3][r] = v.w;
        }
#pragma unroll
        for (int it = 0; it < 4; it++) {
            int id = it * 256 + tid;
            int r = id >> 5, c4 = (id & 31) * 4;
            *(float4*)&Bs[r][c4] = *(const float4*)&W[(k0 + r) * FF + c4];
        }
        __syncthreads();
#pragma unroll
        for (int k = 0; k < 32; k++) {
            float4 a = *(const float4*)&At[k][4 * ty];
            float4 b = *(const float4*)&Bs[k][4 * tx];
            float av[4] = {a.x, a.y, a.z, a.w};
            float bv[4] = {b.x, b.y, b.z, b.w};
#pragma unroll
            for (int r = 0; r < 4; r++)
#pragma unroll
                for (int c = 0; c < 4; c++) acc[r][c] += av[r] * bv[c];
        }
        __syncthreads();
    }
#pragma unroll
    for (int r = 0; r < 4; r++) {
        int row = row0 + 4 * ty + r;
        float4 v = make_float4(acc[r][0], acc[r][1], acc[r][2], acc[r][3]);
        *(float4*)&d_Wh[(size_t)row * FF + 4 * tx] = v;
        uint2 h2, l2;
        h2.x = packhf(v.x, v.y);
        h2.y = packhf(v.z, v.w);
        l2.x = packhf(v.x - f16r(v.x), v.y - f16r(v.y));
        l2.y = packhf(v.z - f16r(v.z), v.w - f16r(v.w));
        size_t woff = ((size_t)row * 16 + (tx >> 1)) * 4 + (tx & 1) * 2;
        *(uint2*)((uint32_t*)d_iJh + woff) = h2;
        *(uint2*)((uint32_t*)d_iJl + woff) = l2;
    }
}

// ---------------- image builder (A tiles, gathered) ----------------
__global__ void k_imgA() {
    int idx = blockIdx.x * 256 + threadIdx.x;
    int tile = idx >> 11, gc = idx & 2047;
    int cnt = d_count;
    if (tile >= (cnt + 127) >> 7) return;
    int row = gc >> 4, c = gc & 15;
    int ridx = tile * 128 + row; if (ridx >= cnt) ridx = cnt - 1;
    const float* src = &d_Wh[(size_t)d_list[ridx] * FF + c * 8];
    float v[8];
    *(float4*)&v[0] = *(const float4*)&src[0];
    *(float4*)&v[4] = *(const float4*)&src[4];
    uint4 h, l; split8(v, h, l);
    d_iAh[idx] = h; d_iAl[idx] = l;
}

// ---------------- mma.sync fused attention (fp16 emu, A_hi in regs) ----------------
__global__ __launch_bounds__(256, 1) void k_attn() {
    extern __shared__ char smc[];
    uint32_t smb = smem_u32(smc);
    const int tid = threadIdx.x, wid = tid >> 5, lane = tid & 31;
    const int g = lane >> 2, t = lane & 3;
    const int m0 = wid * 16;
    const int cnt = d_count;
    const int ntiles = (cnt + 127) >> 7;
    const int nunits = ntiles * JSPLIT;

    const int arow = m0 + (lane & 15);
    const uint32_t acolx = (lane & 16) ? 16u : 0u;
    const uint32_t abase = smb + (uint32_t)arow * 256;
    const uint32_t arot = (uint32_t)(arow & 7) * 16;

    uint32_t stoff[8];
#pragma unroll
    for (int s = 0; s < 8; s++) {
        int idx = s * 256 + tid;
        int row = idx >> 4, c = idx & 15;
        stoff[s] = (uint32_t)row * 256 + (((uint32_t)c * 16) ^ ((row & 7) * 16));
    }

    for (int u = blockIdx.x; u < nunits; u += gridDim.x) {
        const int tile = u >> 4, sl = u & 15;
        __syncthreads();

        {
            const uint4* gah = &d_iAh[tile * 2048];
            const uint4* gal = &d_iAl[tile * 2048];
            const uint4* gjh = &d_iJh[(sl * 512) * 16];
            const uint4* gjl = &d_iJl[(sl * 512) * 16];
#pragma unroll
            for (int s = 0; s < 8; s++) {
                int idx = s * 256 + tid;
                CPA(smb + SA_HI + stoff[s], gah + idx);
                CPA(smb + SA_LO + stoff[s], gal + idx);
                CPA(smb + SJB(0) + stoff[s], gjh + idx);
                CPA(smb + SJB(0) + 32768 + stoff[s], gjl + idx);
            }
            CPC();
        }

        int rA = tile * 128 + m0 + g;
        int rB = rA + 8;
        int rAc = rA < cnt ? rA : cnt - 1;
        int rBc = rB < cnt ? rB : cnt - 1;

        float O[16][4];
#pragma unroll
        for (int ft = 0; ft < 16; ft++)
            O[ft][0] = O[ft][1] = O[ft][2] = O[ft][3] = 0.f;
        float mr0 = -1e30f, mr1 = -1e30f, l0 = 0.f, l1 = 0.f;

        uint32_t ahr[32];   // A_hi fragments, persistent for the whole unit

#pragma unroll 1
        for (int jt = 0; jt < 4; jt++) {
            const int j0 = sl * 512 + jt * 128;
            const uint32_t sjc = smb + SJB(jt & 1);

            if (jt > 0) __syncthreads();
            if (jt < 3) {
                const uint4* gjh = &d_iJh[(j0 + 128) * 16];
                const uint4* gjl = &d_iJl[(j0 + 128) * 16];
                uint32_t sjn = smb + SJB((jt + 1) & 1);
#pragma unroll
                for (int s = 0; s < 8; s++) {
                    int idx = s * 256 + tid;
                    CPA(sjn + stoff[s], gjh + idx);
                    CPA(sjn + 32768 + stoff[s], gjl + idx);
                }
                CPC();
                CPW(1);
            } else {
                CPW(0);
            }
            __syncthreads();

            if (jt == 0) {
#pragma unroll
                for (int q = 0; q < 8; q++) {
                    uint32_t aoff = ((uint32_t)(q * 32) + acolx) ^ arot;
                    ldsm4(&ahr[4 * q], abase + SA_HI + aoff);
                }
            }

            uint4 awA = *(const uint4*)&d_adjb[rAc * 256 + (j0 >> 5)];
            uint4 awB = *(const uint4*)&d_adjb[rBc * 256 + (j0 >> 5)];
            const uint32_t* wa = &awA.x;
            const uint32_t* wb = &awB.x;

#pragma unroll
            for (int h = 0; h < 2; h++) {
                // ---- GEMM1 (3-pass fp16): S(hi.hi) + C(cross) ----
                float S[8][4], C[8][4];
#pragma unroll
                for (int nt = 0; nt < 8; nt++)
#pragma unroll
                    for (int c = 0; c < 4; c++) { S[nt][c] = 0.f; C[nt][c] = 0.f; }
#pragma unroll 2
                for (int q = 0; q < 8; q++) {
                    uint32_t al[4];
                    uint32_t aoff = ((uint32_t)(q * 32) + acolx) ^ arot;
                    ldsm4(al, abase + SA_LO + aoff);
                    const uint32_t* ah = &ahr[4 * q];
#pragma unroll
                    for (int ntp = 0; ntp < 4; ntp++) {
                        int brow = h * 64 + ntp * 16 + ((lane >> 4) & 1) * 8 + (lane & 7);
                        uint32_t boff = (uint32_t)brow * 256 +
                            (((uint32_t)(q * 32) + ((lane & 8) ? 16u : 0u)) ^ ((brow & 7) * 16));
                        uint32_t bh[4], bl[4];
                        ldsm4(bh, sjc + boff);
                        ldsm4(bl, sjc + 32768 + boff);
                        mma16816(S[2 * ntp],     ah, bh);
                        mma16816(C[2 * ntp],     ah, bl);
                        mma16816(C[2 * ntp],     al, bh);
                        mma16816(S[2 * ntp + 1], ah, bh + 2);
                        mma16816(C[2 * ntp + 1], ah, bl + 2);
                        mma16816(C[2 * ntp + 1], al, bh + 2);
                    }
                }
#pragma unroll
                for (int nt = 0; nt < 8; nt++)
#pragma unroll
                    for (int c = 0; c < 4; c++) S[nt][c] += C[nt][c];

                // ---- masked online softmax ----
                float tmA = -1e30f, tmB = -1e30f;
#pragma unroll
                for (int nt = 0; nt < 8; nt++) {
                    int bp = (h * 64 + nt * 8 + 2 * t) & 31;
                    uint32_t mA = wa[h * 2 + (nt >> 2)] >> bp;
                    uint32_t mB = wb[h * 2 + (nt >> 2)] >> bp;
                    if (mA & 1) tmA = fmaxf(tmA, S[nt][0]);
                    if (mA & 2) tmA = fmaxf(tmA, S[nt][1]);
                    if (mB & 1) tmB = fmaxf(tmB, S[nt][2]);
                    if (mB & 2) tmB = fmaxf(tmB, S[nt][3]);
                }
                tmA = fmaxf(tmA, __shfl_xor_sync(0xffffffffu, tmA, 1));
                tmA = fmaxf(tmA, __shfl_xor_sync(0xffffffffu, tmA, 2));
                tmB = fmaxf(tmB, __shfl_xor_sync(0xffffffffu, tmB, 1));
                tmB = fmaxf(tmB, __shfl_xor_sync(0xffffffffu, tmB, 2));
                float nmA = fmaxf(mr0, tmA), nmB = fmaxf(mr1, tmB);
                float scA = __expf(mr0 - nmA), scB = __expf(mr1 - nmB);
                mr0 = nmA; mr1 = nmB;
                l0 *= scA; l1 *= scB;
#pragma unroll
                for (int ft = 0; ft < 16; ft++) {
                    O[ft][0] *= scA; O[ft][1] *= scA;
                    O[ft][2] *= scB; O[ft][3] *= scB;
                }
                // ---- P = exp(S-m), fp16-packed as GEMM2 A-frags ----
                uint32_t phi[16];
#pragma unroll
                for (int nt = 0; nt < 8; nt++) {
                    int bp = (h * 64 + nt * 8 + 2 * t) & 31;
                    uint32_t mA = wa[h * 2 + (nt >> 2)] >> bp;
                    uint32_t mB = wb[h * 2 + (nt >> 2)] >> bp;
                    float p0 = (mA & 1) ? __expf(S[nt][0] - mr0) : 0.f;
                    float p1 = (mA & 2) ? __expf(S[nt][1] - mr0) : 0.f;
                    float p2 = (mB & 1) ? __expf(S[nt][2] - mr1) : 0.f;
                    float p3 = (mB & 2) ? __expf(S[nt][3] - mr1) : 0.f;
                    l0 += p0 + p1; l1 += p2 + p3;
                    int base = (nt >> 1) * 4 + (nt & 1) * 2;
                    phi[base + 0] = packhf(p0, p1);
                    phi[base + 1] = packhf(p2, p3);
                }
                // ---- GEMM2 (1-pass fp16): O += P . J_hi ----
#pragma unroll
                for (int q2 = 0; q2 < 4; q2++) {
                    int brow = h * 64 + q2 * 16 + (lane & 15);
                    uint32_t brb = (uint32_t)brow * 256;
                    uint32_t rot = (uint32_t)(brow & 7) * 16;
#pragma unroll
                    for (int ftp = 0; ftp < 8; ftp++) {
                        uint32_t boff = brb +
                            (((uint32_t)(ftp * 32) + ((lane & 16) ? 16u : 0u)) ^ rot);
                        uint32_t bh[4];
                        ldsm4t(bh, sjc + boff);
                        mma16816(O[2 * ftp],     &phi[q2 * 4], bh);
                        mma16816(O[2 * ftp + 1], &phi[q2 * 4], bh + 2);
                    }
                }
            }
        }
        // ---- epilogue ----
        l0 += __shfl_xor_sync(0xffffffffu, l0, 1);
        l0 += __shfl_xor_sync(0xffffffffu, l0, 2);
        l1 += __shfl_xor_sync(0xffffffffu, l1, 1);
        l1 += __shfl_xor_sync(0xffffffffu, l1, 2);
        int lrowA = m0 + g, lrowB = m0 + 8 + g;
        if (t == 0) {
            d_pm[u * 128 + lrowA] = mr0; d_pl[u * 128 + lrowA] = l0;
            d_pm[u * 128 + lrowB] = mr1; d_pl[u * 128 + lrowB] = l1;
        }
        size_t baseA = ((size_t)u * 128 + lrowA) * FF + 2 * t;
        size_t baseB = ((size_t)u * 128 + lrowB) * FF + 2 * t;
#pragma unroll
        for (int ft = 0; ft < 16; ft++) {
            *(float2*)&d_pO[baseA + ft * 8] = make_float2(O[ft][0], O[ft][1]);
            *(float2*)&d_pO[baseB + ft * 8] = make_float2(O[ft][2], O[ft][3]);
        }
    }
}

// ---------------- combine partials + elu + L2 normalize ----------------
__global__ __launch_bounds__(128) void k_reduce() {
    int rid = blockIdx.x, cnt = d_count;
    if (rid >= cnt) return;
    int tile = rid >> 7, m = rid & 127;
    int f = threadIdx.x;
    int base = tile * JSPLIT;
    float M = -1e30f;
#pragma unroll
    for (int s = 0; s < JSPLIT; s++) M = fmaxf(M, d_pm[(base + s) * 128 + m]);
    float L = 0.f, acc = 0.f;
#pragma unroll 4
    for (int s = 0; s < JSPLIT; s++) {
        float w = __expf(d_pm[(base + s) * 128 + m] - M);
        L += w * d_pl[(base + s) * 128 + m];
        acc += w * d_pO[((size_t)(base + s) * 128 + m) * FF + f];
    }
    float v = acc / L;
    v = (v > 0.f) ? v : expm1f(v);
    __shared__ float red[4];
    float ssq = v * v;
#pragma unroll
    for (int o = 16; o; o >>= 1) ssq += __shfl_xor_sync(0xffffffffu, ssq, o);
    if ((f & 31) == 0) red[f >> 5] = ssq;
    __syncthreads();
    ssq = red[0] + red[1] + red[2] + red[3];
    float inn = 1.f / fmaxf(sqrtf(ssq), 1e-12f);
    d_Hout[(size_t)d_list[rid] * FF + f] = v * inn;
}

__global__ void k_gather(const int* __restrict__ x, float* __restrict__ out) {
    int id = blockIdx.x * blockDim.x + threadIdx.x;
    if (id < BB * 32) {
        int b = id >> 5;
        int c4 = (id & 31) * 4;
        *(float4*)&out[b * FF + c4] = *(const float4*)&d_Hout[(size_t)x[b] * FF + c4];
    }
}

extern "C" void kernel_launch(void* const* d_in, const int* in_sizes, int n_in,
                              void* d_out, int out_size) {
    const int*   x   = (const int*)d_in[0];
    const int*   adj = (const int*)d_in[1];
    const float* emb = (const float*)d_in[2];
    const float* W   = (const float*)d_in[3];
    float* out = (float*)d_out;

    cudaFuncSetAttribute(k_attn, cudaFuncAttributeMaxDynamicSharedMemorySize, SM_TOTAL);

    k_init<<<32, 256>>>();
    k_mark<<<16, 256>>>(x);
    k_compact<<<32, 256>>>();
    k_wh_adj<<<256 + 4096, 256>>>(emb, W, adj);
    k_imgA<<<256, 256>>>();
    k_attn<<<148, 256, SM_TOTAL>>>();
    k_reduce<<<4096, 128>>>();
    k_gather<<<512, 256>>>(x, out);
}